// round 12
// baseline (speedup 1.0000x reference)
#include <cuda_runtime.h>
#include <math.h>

#define FULL_MASK 0xffffffffu
#define DLEV 5

// Global accumulator state (device allocation forbidden; reset by last block -> graph-replay safe)
__device__ float        g_acc   = 0.0f;
__device__ unsigned int g_count = 0;

// 256-bit load with L2 retention hint (sm_103: evict_last requires v8.b32 form)
__device__ __forceinline__ void ldg256_el(const float* p, float4& lo, float4& hi) {
    unsigned r0, r1, r2, r3, r4, r5, r6, r7;
    asm volatile("ld.global.nc.L2::evict_last.v8.b32 {%0,%1,%2,%3,%4,%5,%6,%7}, [%8];"
                 : "=r"(r0), "=r"(r1), "=r"(r2), "=r"(r3),
                   "=r"(r4), "=r"(r5), "=r"(r6), "=r"(r7)
                 : "l"(p));
    lo.x = __uint_as_float(r0); lo.y = __uint_as_float(r1);
    lo.z = __uint_as_float(r2); lo.w = __uint_as_float(r3);
    hi.x = __uint_as_float(r4); hi.y = __uint_as_float(r5);
    hi.z = __uint_as_float(r6); hi.w = __uint_as_float(r7);
}

__device__ __forceinline__ float max4(float4 q) {
    return fmaxf(fmaxf(q.x, q.y), fmaxf(q.z, q.w));
}

// first element of the 8-float chunk equal to m -> global element index (slot*8 + j)
__device__ __forceinline__ int first_eq_idx8(float4 lo, float4 hi, float m, int slot) {
    int j;
    if      (lo.x == m) j = 0;
    else if (lo.y == m) j = 1;
    else if (lo.z == m) j = 2;
    else if (lo.w == m) j = 3;
    else if (hi.x == m) j = 4;
    else if (hi.y == m) j = 5;
    else if (hi.z == m) j = 6;
    else                j = 7;
    return (slot << 3) + j;
}

// 256 threads = 8 warps = 8 rows/block (one warp per row; 512 blocks = one full wave)
__global__ void __launch_bounds__(256)
hier_loss_kernel(
    const float* __restrict__ y_pred,
    const float* __restrict__ y_true,
    const float* __restrict__ class_weights,
    const int*   __restrict__ path_ids,   // [C, D]
    const int*   __restrict__ path_len,   // [C]
    const int*   __restrict__ sib_start,  // [C, D]
    const int*   __restrict__ sib_size,   // [C, D]
    float* __restrict__ out,
    int B, int C)
{
    const int warp = threadIdx.x >> 5;
    const int lane = threadIdx.x & 31;
    const int row  = blockIdx.x * 8 + warp;

    __shared__ float s_part[8];

    float row_total = 0.0f;

    if (row < B) {
        const float* prow = y_pred + (size_t)row * C;
        const float* trow = y_true + (size_t)row * C;
        const int n8 = C >> 3;                       // 341 for C=2728 (exact)
        // rounds where all 32 lanes have a valid chunk
        const int RND = (n8 >= 32) ? ((n8 - 32) / 32 + 1) : 0;   // 10 for n8=341

        float pv = -INFINITY, tv = -INFINITY;
        int   ps = 0, ts = 0;

        if (RND >= 2) {
            // ---- software-pipelined streaming: loads for round k+2 issued before
            //      round k's compute (3-buffer rotation, unroll 3 renames away copies) ----
            int ia = lane;
            int ib = lane + 32;
            float4 apl, aph, atl, ath, bpl, bph, btl, bth;
            ldg256_el(prow + ((size_t)ia << 3), apl, aph);
            ldg256_el(trow + ((size_t)ia << 3), atl, ath);
            ldg256_el(prow + ((size_t)ib << 3), bpl, bph);
            ldg256_el(trow + ((size_t)ib << 3), btl, bth);

            #pragma unroll 3
            for (int k = 0; k < RND - 2; k++) {
                const int ic = ib + 32;
                float4 cpl, cph, ctl, cth;
                ldg256_el(prow + ((size_t)ic << 3), cpl, cph);
                ldg256_el(trow + ((size_t)ic << 3), ctl, cth);
                float mp = fmaxf(max4(apl), max4(aph));
                float mt = fmaxf(max4(atl), max4(ath));
                if (mp > pv) { pv = mp; ps = ia; }
                if (mt > tv) { tv = mt; ts = ia; }
                ia = ib; apl = bpl; aph = bph; atl = btl; ath = bth;
                ib = ic; bpl = cpl; bph = cph; btl = ctl; bth = cth;
            }
            // drain the two in-flight stages
            float mp = fmaxf(max4(apl), max4(aph));
            float mt = fmaxf(max4(atl), max4(ath));
            if (mp > pv) { pv = mp; ps = ia; }
            if (mt > tv) { tv = mt; ts = ia; }
            mp = fmaxf(max4(bpl), max4(bph));
            mt = fmaxf(max4(btl), max4(bth));
            if (mp > pv) { pv = mp; ps = ib; }
            if (mt > tv) { tv = mt; ts = ib; }
        }
        // remaining chunks (lanes with one extra chunk past the uniform region)
        for (int i = (RND << 5) + lane; i < n8; i += 32) {
            float4 al, ah, bl, bh;
            ldg256_el(prow + ((size_t)i << 3), al, ah);
            ldg256_el(trow + ((size_t)i << 3), bl, bh);
            float ma = fmaxf(max4(al), max4(ah));
            float mb = fmaxf(max4(bl), max4(bh));
            if (ma > pv) { pv = ma; ps = i; }
            if (mb > tv) { tv = mb; ts = i; }
        }
        // scalar remainder with exact indices (none for C=2728; kept for generality)
        float prv = -INFINITY, trv = -INFINITY;
        int   pri = 0x7FFFFFFF, tri = 0x7FFFFFFF;
        for (int c = (n8 << 3) + lane; c < C; c += 32) {
            float a = prow[c];
            float b = trow[c];
            if (a > prv) { prv = a; pri = c; }
            if (b > trv) { trv = b; tri = c; }
        }

        // ---- warp max of values (broadcast) ----
        float wp = fmaxf(pv, prv);
        float wt = fmaxf(tv, trv);
        #pragma unroll
        for (int off = 16; off > 0; off >>= 1) {
            wp = fmaxf(wp, __shfl_xor_sync(FULL_MASK, wp, off));
            wt = fmaxf(wt, __shfl_xor_sync(FULL_MASK, wt, off));
        }

        // ---- pass 2: lanes holding the max reload their chunk (cache-hit);
        //      min over candidates = exact first-index tie-break ----
        int pcand = 0x7FFFFFFF;
        if (pv == wp) {
            float4 lo, hi; ldg256_el(prow + ((size_t)ps << 3), lo, hi);
            pcand = min(pcand, first_eq_idx8(lo, hi, wp, ps));
        }
        if (prv == wp) pcand = min(pcand, pri);
        int tcand = 0x7FFFFFFF;
        if (tv == wt) {
            float4 lo, hi; ldg256_el(trow + ((size_t)ts << 3), lo, hi);
            tcand = min(tcand, first_eq_idx8(lo, hi, wt, ts));
        }
        if (trv == wt) tcand = min(tcand, tri);
        #pragma unroll
        for (int off = 16; off > 0; off >>= 1) {
            pcand = min(pcand, __shfl_xor_sync(FULL_MASK, pcand, off));
            tcand = min(tcand, __shfl_xor_sync(FULL_MASK, tcand, off));
        }

        if (lane == 0) {
            const int pred_top = pcand;
            const int true_top = tcand;
            const int len_p = path_len[pred_top];
            const int len_t = path_len[true_top];
            const int lmin  = (len_p < len_t) ? len_p : len_t;
            const int diff  = (len_p > len_t) ? (len_p - len_t) : (len_t - len_p);

            if (diff != 0) {   // else row_total is exactly 0
                float local = 0.0f;
                #pragma unroll
                for (int l = 0; l < DLEV; l++) {
                    if (l < lmin) {
                        const int start = sib_start[true_top * DLEV + l];
                        const int size  = sib_size [true_top * DLEV + l];
                        const int tid_l = path_ids [true_top * DLEV + l];

                        // lse of (y_pred * 0/1 mask): masked-out classes contribute exp(0)=1
                        float s = (float)(C - size);
                        for (int c = start; c < start + size; c++) {
                            s += expf(prow[c]);      // L1/L2-hot (row just streamed)
                        }
                        const float lse = logf(s);
                        const float ce  = lse - prow[tid_l];
                        const float h   = (float)(len_t - l - 1);
                        local += expf(-0.5f * h) * ce;
                    }
                }
                row_total = local * (1.5f * (float)diff) * class_weights[true_top];
            }
        }
    }

    // ---- block partial sum (8 values) -> one float atomicAdd ----
    if (lane == 0) s_part[warp] = row_total;
    __syncthreads();

    if (threadIdx.x == 0) {
        float part = 0.0f;
        #pragma unroll
        for (int w = 0; w < 8; w++) part += s_part[w];
        atomicAdd(&g_acc, part);
        __threadfence();                          // order value-add before counter-add
        unsigned int done = atomicAdd(&g_count, 1u);
        if (done == gridDim.x - 1) {
            __threadfence();                      // acquire
            float total = atomicAdd(&g_acc, 0.0f);    // atomic read at L2
            out[0] = total / (float)B;
            g_acc   = 0.0f;
            g_count = 0;                          // reset for next graph replay
        }
    }
}

extern "C" void kernel_launch(void* const* d_in, const int* in_sizes, int n_in,
                              void* d_out, int out_size)
{
    const float* y_pred        = (const float*)d_in[0];
    const float* y_true        = (const float*)d_in[1];
    const float* class_weights = (const float*)d_in[2];
    const int*   path_ids      = (const int*)  d_in[3];
    const int*   path_len      = (const int*)  d_in[4];
    const int*   sib_start     = (const int*)  d_in[5];
    const int*   sib_size      = (const int*)  d_in[6];

    const int C = in_sizes[2];            // 2728
    const int B = in_sizes[0] / C;        // 4096

    const int blocks = (B + 7) / 8;       // 512: 8 rows/block, one warp per row

    hier_loss_kernel<<<blocks, 256>>>(
        y_pred, y_true, class_weights, path_ids, path_len, sib_start, sib_size,
        (float*)d_out, B, C);
}

// round 13
// speedup vs baseline: 1.4289x; 1.4289x over previous
#include <cuda_runtime.h>
#include <math.h>

#define FULL_MASK 0xffffffffu
#define DLEV 5

// Global accumulator state (device allocation forbidden; reset by last block -> graph-replay safe)
__device__ float        g_acc   = 0.0f;
__device__ unsigned int g_count = 0;

// 256-bit load with L2 retention hint (sm_103: evict_last requires v8.b32 form)
__device__ __forceinline__ void ldg256_el(const float* p, float4& lo, float4& hi) {
    unsigned r0, r1, r2, r3, r4, r5, r6, r7;
    asm volatile("ld.global.nc.L2::evict_last.v8.b32 {%0,%1,%2,%3,%4,%5,%6,%7}, [%8];"
                 : "=r"(r0), "=r"(r1), "=r"(r2), "=r"(r3),
                   "=r"(r4), "=r"(r5), "=r"(r6), "=r"(r7)
                 : "l"(p));
    lo.x = __uint_as_float(r0); lo.y = __uint_as_float(r1);
    lo.z = __uint_as_float(r2); lo.w = __uint_as_float(r3);
    hi.x = __uint_as_float(r4); hi.y = __uint_as_float(r5);
    hi.z = __uint_as_float(r6); hi.w = __uint_as_float(r7);
}

__device__ __forceinline__ float max4(float4 q) {
    return fmaxf(fmaxf(q.x, q.y), fmaxf(q.z, q.w));
}

// first element of the 8-float chunk equal to m -> global element index (slot*8 + j)
__device__ __forceinline__ int first_eq_idx8(float4 lo, float4 hi, float m, int slot) {
    int j;
    if      (lo.x == m) j = 0;
    else if (lo.y == m) j = 1;
    else if (lo.z == m) j = 2;
    else if (lo.w == m) j = 3;
    else if (hi.x == m) j = 4;
    else if (hi.y == m) j = 5;
    else if (hi.z == m) j = 6;
    else                j = 7;
    return (slot << 3) + j;
}

// 256 threads = 8 warps; 592 blocks (148 SMs x 4) -> uniform 4 blocks/SM.
// Rows assigned proportionally across all 4736 global warps so idle slots
// are scattered uniformly (~4.3 per SM) instead of clustering on whole SMs.
__global__ void __launch_bounds__(256)
hier_loss_kernel(
    const float* __restrict__ y_pred,
    const float* __restrict__ y_true,
    const float* __restrict__ class_weights,
    const int*   __restrict__ path_ids,   // [C, D]
    const int*   __restrict__ path_len,   // [C]
    const int*   __restrict__ sib_start,  // [C, D]
    const int*   __restrict__ sib_size,   // [C, D]
    float* __restrict__ out,
    int B, int C)
{
    const int warp = threadIdx.x >> 5;
    const int lane = threadIdx.x & 31;

    // proportional row assignment: warp g handles row lo iff hi > lo
    const int G   = gridDim.x * 8;                       // total warps (4736)
    const int g   = blockIdx.x * 8 + warp;
    const int lo  = (int)(((long long)g       * B) / G);
    const int hi  = (int)(((long long)(g + 1) * B) / G);
    const int row = lo;
    const bool active = (hi > lo);

    __shared__ float s_part[8];

    float row_total = 0.0f;

    if (active) {
        const float* prow = y_pred + (size_t)row * C;
        const float* trow = y_true + (size_t)row * C;
        const int n8 = C >> 3;  // 341 for C=2728 (exact: 341*8 = 2728)

        // ---- pass 1: values-only max over 32B chunks, 2 trackers/tensor,
        //      evict_last retains the 89MB working set in L2 across graph replays ----
        float pv0 = -INFINITY, pv1 = -INFINITY, tv0 = -INFINITY, tv1 = -INFINITY;
        int   ps0 = 0, ps1 = 0, ts0 = 0, ts1 = 0;

        int i = lane;
        for (; i + 32 < n8; i += 64) {
            float4 a0l, a0h, a1l, a1h, b0l, b0h, b1l, b1h;
            ldg256_el(prow + ((size_t)i << 3),        a0l, a0h);
            ldg256_el(prow + ((size_t)(i + 32) << 3), a1l, a1h);
            ldg256_el(trow + ((size_t)i << 3),        b0l, b0h);
            ldg256_el(trow + ((size_t)(i + 32) << 3), b1l, b1h);
            float ma0 = fmaxf(max4(a0l), max4(a0h));
            float ma1 = fmaxf(max4(a1l), max4(a1h));
            float mb0 = fmaxf(max4(b0l), max4(b0h));
            float mb1 = fmaxf(max4(b1l), max4(b1h));
            if (ma0 > pv0) { pv0 = ma0; ps0 = i;      }
            if (ma1 > pv1) { pv1 = ma1; ps1 = i + 32; }
            if (mb0 > tv0) { tv0 = mb0; ts0 = i;      }
            if (mb1 > tv1) { tv1 = mb1; ts1 = i + 32; }
        }
        for (; i < n8; i += 32) {
            float4 al, ah, bl, bh;
            ldg256_el(prow + ((size_t)i << 3), al, ah);
            ldg256_el(trow + ((size_t)i << 3), bl, bh);
            float ma = fmaxf(max4(al), max4(ah));
            float mb = fmaxf(max4(bl), max4(bh));
            if (ma > pv0) { pv0 = ma; ps0 = i; }
            if (mb > tv0) { tv0 = mb; ts0 = i; }
        }
        // scalar remainder with exact indices (none for C=2728; kept for generality)
        float prv = -INFINITY, trv = -INFINITY;
        int   pri = 0x7FFFFFFF, tri = 0x7FFFFFFF;
        for (int c = (n8 << 3) + lane; c < C; c += 32) {
            float a = prow[c];
            float b = trow[c];
            if (a > prv) { prv = a; pri = c; }
            if (b > trv) { trv = b; tri = c; }
        }

        // ---- warp max of values (broadcast) ----
        float wp = fmaxf(fmaxf(pv0, pv1), prv);
        float wt = fmaxf(fmaxf(tv0, tv1), trv);
        #pragma unroll
        for (int off = 16; off > 0; off >>= 1) {
            wp = fmaxf(wp, __shfl_xor_sync(FULL_MASK, wp, off));
            wt = fmaxf(wt, __shfl_xor_sync(FULL_MASK, wt, off));
        }

        // ---- pass 2: trackers holding the max reload their chunk (L1-hit);
        //      min over candidates = exact first-index tie-break ----
        int pcand = 0x7FFFFFFF;
        if (pv0 == wp) {
            float4 qlo, qhi; ldg256_el(prow + ((size_t)ps0 << 3), qlo, qhi);
            pcand = min(pcand, first_eq_idx8(qlo, qhi, wp, ps0));
        }
        if (pv1 == wp) {
            float4 qlo, qhi; ldg256_el(prow + ((size_t)ps1 << 3), qlo, qhi);
            pcand = min(pcand, first_eq_idx8(qlo, qhi, wp, ps1));
        }
        if (prv == wp) pcand = min(pcand, pri);
        int tcand = 0x7FFFFFFF;
        if (tv0 == wt) {
            float4 qlo, qhi; ldg256_el(trow + ((size_t)ts0 << 3), qlo, qhi);
            tcand = min(tcand, first_eq_idx8(qlo, qhi, wt, ts0));
        }
        if (tv1 == wt) {
            float4 qlo, qhi; ldg256_el(trow + ((size_t)ts1 << 3), qlo, qhi);
            tcand = min(tcand, first_eq_idx8(qlo, qhi, wt, ts1));
        }
        if (trv == wt) tcand = min(tcand, tri);
        #pragma unroll
        for (int off = 16; off > 0; off >>= 1) {
            pcand = min(pcand, __shfl_xor_sync(FULL_MASK, pcand, off));
            tcand = min(tcand, __shfl_xor_sync(FULL_MASK, tcand, off));
        }

        if (lane == 0) {
            const int pred_top = pcand;
            const int true_top = tcand;
            const int len_p = path_len[pred_top];
            const int len_t = path_len[true_top];
            const int lmin  = (len_p < len_t) ? len_p : len_t;
            const int diff  = (len_p > len_t) ? (len_p - len_t) : (len_t - len_p);

            if (diff != 0) {   // else row_total is exactly 0
                float local = 0.0f;
                #pragma unroll
                for (int l = 0; l < DLEV; l++) {
                    if (l < lmin) {
                        const int start = sib_start[true_top * DLEV + l];
                        const int size  = sib_size [true_top * DLEV + l];
                        const int tid_l = path_ids [true_top * DLEV + l];

                        // lse of (y_pred * 0/1 mask): masked-out classes contribute exp(0)=1
                        float s = (float)(C - size);
                        for (int c = start; c < start + size; c++) {
                            s += expf(prow[c]);      // L1/L2-hot (row just streamed)
                        }
                        const float lse = logf(s);
                        const float ce  = lse - prow[tid_l];
                        const float h   = (float)(len_t - l - 1);
                        local += expf(-0.5f * h) * ce;
                    }
                }
                row_total = local * (1.5f * (float)diff) * class_weights[true_top];
            }
        }
    }

    // ---- block partial sum (8 values) -> one float atomicAdd ----
    if (lane == 0) s_part[warp] = row_total;
    __syncthreads();

    if (threadIdx.x == 0) {
        float part = 0.0f;
        #pragma unroll
        for (int w = 0; w < 8; w++) part += s_part[w];
        atomicAdd(&g_acc, part);
        __threadfence();                          // order value-add before counter-add
        unsigned int done = atomicAdd(&g_count, 1u);
        if (done == gridDim.x - 1) {
            __threadfence();                      // acquire
            float total = atomicAdd(&g_acc, 0.0f);    // atomic read at L2
            out[0] = total / (float)B;
            g_acc   = 0.0f;
            g_count = 0;                          // reset for next graph replay
        }
    }
}

extern "C" void kernel_launch(void* const* d_in, const int* in_sizes, int n_in,
                              void* d_out, int out_size)
{
    const float* y_pred        = (const float*)d_in[0];
    const float* y_true        = (const float*)d_in[1];
    const float* class_weights = (const float*)d_in[2];
    const int*   path_ids      = (const int*)  d_in[3];
    const int*   path_len      = (const int*)  d_in[4];
    const int*   sib_start     = (const int*)  d_in[5];
    const int*   sib_size      = (const int*)  d_in[6];

    const int C = in_sizes[2];            // 2728
    const int B = in_sizes[0] / C;        // 4096

    const int blocks = 148 * 4;           // 592: uniform 4 blocks/SM, one full wave

    hier_loss_kernel<<<blocks, 256>>>(
        y_pred, y_true, class_weights, path_ids, path_len, sib_start, sib_size,
        (float*)d_out, B, C);
}